// round 8
// baseline (speedup 1.0000x reference)
#include <cuda_runtime.h>
#include <cstdint>
#include <cstddef>

#define NVEC 1024
#define NDIM 64
#define NHID 32
#define NW   10
#define NB   16
#define NOFF 11

// Scratch (no allocations allowed): device globals.
__device__ float g_w[NW * NB * NOFF * NVEC];   // sparse W values [i][b][o][n]
__device__ float g_fWT3[10 * 16 * NVEC * 4];   // finW as [c][dg][n][4] (2.6MB)
__device__ float g_part[NB * 8 * 10];          // partial sums for output GEMM
__device__ int   g_cnt;                        // block completion counter

// ---------- f32x2 packed helpers (sm_103a FFMA2) ----------
__device__ __forceinline__ unsigned long long pack2(float x, float y) {
    unsigned long long r;
    asm("mov.b64 %0, {%1, %2};" : "=l"(r) : "f"(x), "f"(y));
    return r;
}
__device__ __forceinline__ void fma2(unsigned long long& d, unsigned long long a, unsigned long long b) {
    asm("fma.rn.f32x2 %0, %1, %2, %0;" : "+l"(d) : "l"(a), "l"(b));
}
__device__ __forceinline__ float2 unpack2(unsigned long long v) {
    float lo, hi;
    asm("mov.b64 {%0, %1}, %2;" : "=f"(lo), "=f"(hi) : "l"(v));
    return make_float2(lo, hi);
}
__device__ __forceinline__ float gelu_exact(float x) {
    return 0.5f * x * (1.0f + erff(x * 0.70710678f));
}

// ---------------------------------------------------------------------------
// FUSED precompute: persistent grid of 148 blocks x 1024 threads.
// 672 work items, statically range-partitioned (contiguous, i-major):
//   items [0,640):   (i, b, quarter) -> h-GEMM in registers + sparse-W2 dots
//   items [640,672): finW transpose tiles -> g_fWT3 (consumed by recurse_kernel)
// smem: full fW2 layer sfT[1024][33] (odd stride: conflict-free stage + read),
//       sw1[64][32], fb1, fb2, and Xs[256][17] / P[4][256][13] (overlaid).
// H never leaves registers/smem -> no 21MB global round-trip, no extra launch.
// ---------------------------------------------------------------------------
#define FTS 33
#define OFF_SW1  (NVEC * FTS)                       // 33792
#define OFF_FB1  (OFF_SW1 + NDIM * NHID)            // 35840
#define OFF_FB2  (OFF_FB1 + NHID)                   // 35872
#define OFF_XSP  (OFF_FB2 + NVEC)                   // 36896
#define P_SZ     (4 * 256 * 13)                     // 13312
#define FUSED_SMEM ((OFF_XSP + P_SZ) * 4)           // 200832 B

#define N_HEAVY  640
#define N_ITEMS  672

__global__ void __launch_bounds__(1024, 1) fused_kernel(
    const float* __restrict__ data, const float* __restrict__ fW1,
    const float* __restrict__ fb1,  const float* __restrict__ fW2,
    const float* __restrict__ fb2,  const float* __restrict__ finW)
{
    extern __shared__ float sm[];
    float* sfT  = sm;                 // [1024][33]
    float* sw1  = sm + OFF_SW1;       // [64][32]
    float* sfb1 = sm + OFF_FB1;       // [32]
    float* sfb2 = sm + OFF_FB2;       // [1024]
    float* Xs   = sm + OFF_XSP;       // [256][17]  (h-phase)
    float* P    = sm + OFF_XSP;       // [4][256][13] (w2 combine, overlaid)

    const int t  = threadIdx.x;
    const int B  = blockIdx.x;
    const int lo = (B * N_ITEMS) / 148;
    const int hi = ((B + 1) * N_ITEMS) / 148;
    const int row = t & 255;
    const int hh  = t >> 8;           // 0..3, owns h-slice [8*hh, 8*hh+8)
    const int OFF[NOFF] = {0, 1, 2, 4, 8, 16, 32, 64, 128, 256, 512};

    int previ = -1;

#pragma unroll 1
    for (int item = lo; item < hi; item++) {
        // -------------------- finW transpose items --------------------
        if (item >= N_HEAVY) {
            __syncthreads();                    // done with sfT etc.
            float* sF = sm;                     // [2048][11] = 22528 floats
            const int tile = item - N_HEAVY;    // 0..31
            const int f0   = tile * 2048;
            const int n00  = tile * 32;
            const float4* src =
                reinterpret_cast<const float4*>(finW + (size_t)f0 * 10);
#pragma unroll
            for (int jj = 0; jj < 5; jj++) {    // 5120 float4
                int p = t + 1024 * jj;
                float4 v = __ldg(src + p);
                float vals[4] = {v.x, v.y, v.z, v.w};
#pragma unroll
                for (int u = 0; u < 4; u++) {
                    int e  = 4 * p + u;
                    int fl = e / 10, cc = e - 10 * fl;
                    sF[fl * 11 + cc] = vals[u];
                }
            }
            __syncthreads();
            float4* dst = reinterpret_cast<float4*>(g_fWT3);
#pragma unroll
            for (int jj = 0; jj < 5; jj++) {    // 5120 outputs
                int oi = t + 1024 * jj;
                int cc = oi >> 9;               // 0..9
                int r  = oi & 511;
                int dg = r >> 5, nn = r & 31;
                float4 v;
                v.x = sF[(nn * 64 + dg * 4 + 0) * 11 + cc];
                v.y = sF[(nn * 64 + dg * 4 + 1) * 11 + cc];
                v.z = sF[(nn * 64 + dg * 4 + 2) * 11 + cc];
                v.w = sF[(nn * 64 + dg * 4 + 3) * 11 + cc];
                dst[(cc * 16 + dg) * 1024 + n00 + nn] = v;
            }
            __syncthreads();
            previ = -1;                         // sfT destroyed
            continue;
        }

        // -------------------- heavy item: (i, b, quarter) --------------------
        const int i  = item >> 6;
        const int j  = item & 63;
        const int b  = j >> 2;
        const int q  = j & 3;
        const int n0 = q * 256;

        if (i != previ) {
            __syncthreads();                    // prior readers of sfT/P done
            sw1[t]        = fW1[i * 2048 + t];
            sw1[t + 1024] = fW1[i * 2048 + 1024 + t];
            if (t < NHID) sfb1[t] = fb1[i * NHID + t];
            sfb2[t] = fb2[i * NVEC + t];
            // stage fW2 layer with transposing STS: coalesced LDG along n,
            // STS stride 33 (odd) -> conflict-free.
#pragma unroll
            for (int h = 0; h < NHID; h++)
                sfT[t * FTS + h] = __ldg(&fW2[((size_t)i * NHID + h) * NVEC + t]);
            __syncthreads();
            previ = i;
        }

        // ---- h-phase: thread computes h[n][8hh..8hh+8) in registers ----
        unsigned long long acc[4] = {0ull, 0ull, 0ull, 0ull};
        const float4* src4 = reinterpret_cast<const float4*>(
            data + ((size_t)b * NVEC + n0) * NDIM);

#pragma unroll 1
        for (int c = 0; c < 4; c++) {
            __syncthreads();                    // Xs free (prev chunk / prev item P)
            {   // stage X chunk: 256 rows x 16 k = 1024 float4
                int r = t >> 2, s = t & 3;
                float4 v = __ldg(src4 + r * 16 + c * 4 + s);
                float* d = Xs + r * 17 + 4 * s;
                d[0] = v.x; d[1] = v.y; d[2] = v.z; d[3] = v.w;
            }
            __syncthreads();
#pragma unroll
            for (int kk = 0; kk < 16; kk++) {
                const unsigned long long* wp =
                    reinterpret_cast<const unsigned long long*>(
                        &sw1[(c * 16 + kk) * NHID + hh * 8]);
                unsigned long long w0 = wp[0], w1 = wp[1], w2_ = wp[2], w3 = wp[3];
                float xv = Xs[row * 17 + kk];
                unsigned long long xx = pack2(xv, xv);
                fma2(acc[0], xx, w0);
                fma2(acc[1], xx, w1);
                fma2(acc[2], xx, w2_);
                fma2(acc[3], xx, w3);
            }
        }

        // bias + gelu (exact erf)
        float hreg[8];
        {
            const unsigned long long* bp =
                reinterpret_cast<const unsigned long long*>(&sfb1[hh * 8]);
#pragma unroll
            for (int p = 0; p < 4; p++) {
                float2 v  = unpack2(acc[p]);
                float2 bb = unpack2(bp[p]);
                hreg[2 * p]     = gelu_exact(v.x + bb.x);
                hreg[2 * p + 1] = gelu_exact(v.y + bb.y);
            }
        }

        // ---- w2-phase: 11 chord dots over this thread's 8-h slice ----
        const int n = n0 + row;
        __syncthreads();                        // Xs reads done -> P overlay safe
#pragma unroll
        for (int o = 0; o < NOFF; o++) {
            int m = (n + OFF[o]) & (NVEC - 1);
            const float* Tp = &sfT[m * FTS + hh * 8];
            float s = 0.f;
#pragma unroll
            for (int qq = 0; qq < 8; qq++) s = fmaf(hreg[qq], Tp[qq], s);
            P[(hh * 256 + row) * 13 + o] = s;
        }
        __syncthreads();
        // combine 4 partials + bias, balanced across all threads
#pragma unroll
        for (int l = 0; l < 3; l++) {
            int task = t + 1024 * l;            // 2816 tasks = 11 o x 256 rows
            if (task < NOFF * 256) {
                int o  = task >> 8;
                int rr = task & 255;
                int m  = (n0 + rr + OFF[o]) & (NVEC - 1);
                float s = P[(0 * 256 + rr) * 13 + o] + P[(1 * 256 + rr) * 13 + o]
                        + P[(2 * 256 + rr) * 13 + o] + P[(3 * 256 + rr) * 13 + o]
                        + sfb2[m];
                g_w[((size_t)(i * NB + b) * NOFF + o) * NVEC + n0 + rr] = s;
            }
        }
    }
}

// ---------------------------------------------------------------------------
// Kernel 2: 10-layer sparse recursion + FUSED output GEMM epilogue.
// ---------------------------------------------------------------------------
__global__ void __launch_bounds__(1024) recurse_kernel(
    const float* __restrict__ data, const float* __restrict__ finb,
    float* __restrict__ out)
{
    __shared__ float Vs[2][8 * NVEC];
    __shared__ int isLast;
    const int t  = threadIdx.x;
    const int d0 = blockIdx.x * 8;
    const int b  = blockIdx.y;

    const float4* p =
        reinterpret_cast<const float4*>(data + ((size_t)(b * NVEC) + t) * NDIM + d0);
    float4 A  = __ldg(p);
    float4 Bv = __ldg(p + 1);
    float acc[8] = {A.x, A.y, A.z, A.w, Bv.x, Bv.y, Bv.z, Bv.w};
#pragma unroll
    for (int d = 0; d < 8; d++) Vs[0][d * NVEC + t] = acc[d];

    const int OFF[NOFF] = {0, 1, 2, 4, 8, 16, 32, 64, 128, 256, 512};
    float wv[NOFF];
    {
        const float* w = g_w + (size_t)((9 * NB + b) * NOFF) * NVEC;
#pragma unroll
        for (int o = 0; o < NOFF; o++) wv[o] = __ldg(&w[o * NVEC + t]);
    }
    __syncthreads();

    int cur = 0;
#pragma unroll
    for (int i = NW - 1; i >= 0; i--) {
        float wn[NOFF];
        if (i > 0) {
            const float* w = g_w + (size_t)(((i - 1) * NB + b) * NOFF) * NVEC;
#pragma unroll
            for (int o = 0; o < NOFF; o++) wn[o] = __ldg(&w[o * NVEC + t]);
        }

        float na[8];
#pragma unroll
        for (int d = 0; d < 8; d++)
            na[d] = acc[d] + wv[0] * acc[d];
#pragma unroll
        for (int o = 1; o < NOFF; o++) {
            int m = (t + OFF[o]) & (NVEC - 1);
#pragma unroll
            for (int d = 0; d < 8; d++) na[d] += wv[o] * Vs[cur][d * NVEC + m];
        }
#pragma unroll
        for (int d = 0; d < 8; d++) {
            Vs[cur ^ 1][d * NVEC + t] = na[d];
            acc[d] = na[d];
        }
        __syncthreads();
        cur ^= 1;
#pragma unroll
        for (int o = 0; o < NOFF; o++) wv[o] = wn[o];
    }

    // ---- fused output GEMM epilogue ----
    const float4* W3 = reinterpret_cast<const float4*>(g_fWT3);
    const int dg0 = blockIdx.x * 2;
    float cs[10];
#pragma unroll
    for (int c = 0; c < 10; c++) {
        float4 w0 = __ldg(&W3[(c * 16 + dg0) * 1024 + t]);
        float4 w1 = __ldg(&W3[(c * 16 + dg0 + 1) * 1024 + t]);
        float s = acc[0] * w0.x + acc[1] * w0.y + acc[2] * w0.z + acc[3] * w0.w;
        s += acc[4] * w1.x + acc[5] * w1.y + acc[6] * w1.z + acc[7] * w1.w;
        cs[c] = s;
    }

#pragma unroll
    for (int c = 0; c < 10; c++) {
#pragma unroll
        for (int s = 16; s > 0; s >>= 1)
            cs[c] += __shfl_xor_sync(0xffffffffu, cs[c], s);
    }
    float* red = &Vs[0][0];
    int lane = t & 31, wp = t >> 5;
    if (lane == 0) {
#pragma unroll
        for (int c = 0; c < 10; c++) red[wp * 10 + c] = cs[c];
    }
    __syncthreads();
    if (t < 10) {
        float s = 0.f;
        for (int w_ = 0; w_ < 32; w_++) s += red[w_ * 10 + t];
        g_part[(b * 8 + blockIdx.x) * 10 + t] = s;
    }
    __threadfence();
    if (t == 0) {
        int old = atomicAdd(&g_cnt, 1);
        isLast = (old == NB * 8 - 1);
    }
    __syncthreads();
    if (isLast) {
        __threadfence();
        if (t == 0) g_cnt = 0;
        if (t < NB * 10) {
            int bb = t / 10, c = t - bb * 10;
            float s = __ldg(&finb[c]);
#pragma unroll
            for (int cc = 0; cc < 8; cc++) s += g_part[(bb * 8 + cc) * 10 + c];
            out[t] = s;
        }
    }
}

// ---------------------------------------------------------------------------
extern "C" void kernel_launch(void* const* d_in, const int* in_sizes, int n_in,
                              void* d_out, int out_size)
{
    const float* data = (const float*)d_in[0];
    const float* fW1  = (const float*)d_in[1];
    const float* fb1  = (const float*)d_in[2];
    const float* fW2  = (const float*)d_in[3];
    const float* fb2  = (const float*)d_in[4];
    const float* finW = (const float*)d_in[5];
    const float* finb = (const float*)d_in[6];
    float* out = (float*)d_out;

    cudaFuncSetAttribute(fused_kernel,
                         cudaFuncAttributeMaxDynamicSharedMemorySize, FUSED_SMEM);

    fused_kernel<<<148, 1024, FUSED_SMEM>>>(data, fW1, fb1, fW2, fb2, finW);
    recurse_kernel<<<dim3(8, 16), 1024>>>(data, finb, out);
}

// round 9
// speedup vs baseline: 1.1034x; 1.1034x over previous
#include <cuda_runtime.h>
#include <cstdint>
#include <cstddef>

#define NVEC 1024
#define NDIM 64
#define NHID 32
#define NW   10
#define NB   16
#define NOFF 11

// Scratch (no allocations allowed): device globals.
__device__ float g_w[NW * NB * NOFF * NVEC];   // sparse W values [i][b][o][n]
__device__ float g_H[NW * NB * NVEC * NHID];   // gelu hidden activations (21MB)
__device__ float g_fW2T[NW * NVEC * NHID];     // fW2 transposed [i][n][h]
__device__ float g_fWT3[10 * 16 * NVEC * 4];   // finW as [c][dg][n][4] (2.6MB)
__device__ float g_part[NB * 16 * 10];         // partial sums for output GEMM
__device__ int   g_cnt;                        // block completion counter

// ---------- f32x2 packed helpers (sm_103a FFMA2) ----------
__device__ __forceinline__ unsigned long long pack2(float x, float y) {
    unsigned long long r;
    asm("mov.b64 %0, {%1, %2};" : "=l"(r) : "f"(x), "f"(y));
    return r;
}
__device__ __forceinline__ void fma2(unsigned long long& d, unsigned long long a, unsigned long long b) {
    asm("fma.rn.f32x2 %0, %1, %2, %0;" : "+l"(d) : "l"(a), "l"(b));
}
__device__ __forceinline__ float2 unpack2(unsigned long long v) {
    float lo, hi;
    asm("mov.b64 {%0, %1}, %2;" : "=f"(lo), "=f"(hi) : "l"(v));
    return make_float2(lo, hi);
}
__device__ __forceinline__ float gelu_exact(float x) {
    return 0.5f * x * (1.0f + erff(x * 0.70710678f));
}

// ---------------------------------------------------------------------------
// Kernel A: H = gelu(X @ fW1 + fb1), 4n x 8h register tile, 256 threads,
// k CHUNKED (4 x 16) -> Xs[256][17], 25.7KB smem, 4 CTAs/SM.
// z == 10: transpose fW2 -> g_fW2T.   z == 11: finW -> g_fWT3 (4 sub-tiles).
// ---------------------------------------------------------------------------
#define XS 17
#define H_SMEM ((256 * XS + NDIM * NHID + NHID) * 4)   // 25728 B

__global__ void __launch_bounds__(256, 4) h_kernel(
    const float* __restrict__ data, const float* __restrict__ fW1,
    const float* __restrict__ fb1,  const float* __restrict__ fW2,
    const float* __restrict__ finW)
{
    extern __shared__ float sm[];
    const int t = threadIdx.x;

    // ---------------- fW2 transpose branch ----------------
    if (blockIdx.z == NW) {
        int idx = blockIdx.y * 4 + blockIdx.x;     // 0..63
        if (idx >= 2 * NW) return;
        const int i  = idx >> 1;
        const int c0 = (idx & 1) * 512;
        float* tile = sm;                          // [32][33]
        for (int s = 0; s < 16; s++) {
#pragma unroll
            for (int it = 0; it < 4; it++) {
                int r = it * 8 + (t >> 5);
                int c = t & 31;
                if (r < 32)
                    tile[r * 33 + c] = fW2[((size_t)(i * NHID) + r) * NVEC + c0 + s * 32 + c];
            }
            __syncthreads();
            int cr = t >> 3, rg = t & 7;
            float4 v = make_float4(tile[(4 * rg + 0) * 33 + cr],
                                   tile[(4 * rg + 1) * 33 + cr],
                                   tile[(4 * rg + 2) * 33 + cr],
                                   tile[(4 * rg + 3) * 33 + cr]);
            *reinterpret_cast<float4*>(
                &g_fW2T[((size_t)(i * NVEC) + c0 + s * 32 + cr) * NHID + 4 * rg]) = v;
            __syncthreads();
        }
        return;
    }

    // ------------- finW transpose branch: [f][10] -> [c][dg][n][4] ----------
    if (blockIdx.z == NW + 1) {
        int idx = blockIdx.y * 4 + blockIdx.x;     // 0..63
        float* sF = sm;                            // [256][11]
        float4* dst = reinterpret_cast<float4*>(g_fWT3);
#pragma unroll 1
        for (int s = 0; s < 4; s++) {
            const int fbase = idx * 1024 + s * 256;
            const int nbase = (idx * 16) + s * 4;
            const float4* src =
                reinterpret_cast<const float4*>(finW + (size_t)fbase * 10);
#pragma unroll
            for (int j = 0; j < 3; j++) {
                int p = t + 256 * j;
                if (p < 640) {
                    float4 v = __ldg(src + p);
                    float vals[4] = {v.x, v.y, v.z, v.w};
#pragma unroll
                    for (int u = 0; u < 4; u++) {
                        int e  = 4 * p + u;
                        int fl = e / 10, c = e - 10 * fl;
                        sF[fl * 11 + c] = vals[u];
                    }
                }
            }
            __syncthreads();
#pragma unroll
            for (int j = 0; j < 3; j++) {
                int oi = t + 256 * j;
                if (oi < 640) {
                    int c  = oi / 64;
                    int r  = oi - 64 * c;
                    int dg = r >> 2, nn = r & 3;
                    float4 v;
                    v.x = sF[(nn * 64 + 4 * dg + 0) * 11 + c];
                    v.y = sF[(nn * 64 + 4 * dg + 1) * 11 + c];
                    v.z = sF[(nn * 64 + 4 * dg + 2) * 11 + c];
                    v.w = sF[(nn * 64 + 4 * dg + 3) * 11 + c];
                    dst[(c * 16 + dg) * 1024 + nbase + nn] = v;
                }
            }
            __syncthreads();
        }
        return;
    }

    // ---------------- H branch ----------------
    float* Xs   = sm;                   // [256][17]
    float* sw1  = Xs + 256 * XS;        // [64][32]
    float* sfb1 = sw1 + NDIM * NHID;    // [32]

    const int n0 = blockIdx.x * 256;
    const int b  = blockIdx.y;
    const int i  = blockIdx.z;

    for (int idx = t; idx < NDIM * NHID; idx += 256)
        sw1[idx] = fW1[i * NDIM * NHID + idx];
    if (t < NHID) sfb1[t] = fb1[i * NHID + t];

    const int ht8 = (t & 3) * 8;
    const int nb  = (t >> 2) * 4;
    const float4* src =
        reinterpret_cast<const float4*>(data + ((size_t)b * NVEC + n0) * NDIM);

    unsigned long long acc[4][4];
#pragma unroll
    for (int j = 0; j < 4; j++)
#pragma unroll
        for (int p = 0; p < 4; p++) acc[j][p] = 0ull;

#pragma unroll 1
    for (int c = 0; c < 4; c++) {
#pragma unroll
        for (int j = 0; j < 4; j++) {
            int q   = t + 256 * j;
            int row = q >> 2, sub = q & 3;
            float4 v = __ldg(src + row * 16 + c * 4 + sub);
            float* d = Xs + row * XS + sub * 4;
            d[0] = v.x; d[1] = v.y; d[2] = v.z; d[3] = v.w;
        }
        __syncthreads();

#pragma unroll
        for (int kk = 0; kk < 16; kk++) {
            int k = 16 * c + kk;
            const unsigned long long* wp =
                reinterpret_cast<const unsigned long long*>(&sw1[k * NHID + ht8]);
            unsigned long long w0 = wp[0], w1 = wp[1], w2 = wp[2], w3 = wp[3];
#pragma unroll
            for (int j = 0; j < 4; j++) {
                float xv = Xs[(nb + j) * XS + kk];
                unsigned long long xx = pack2(xv, xv);
                fma2(acc[j][0], xx, w0);
                fma2(acc[j][1], xx, w1);
                fma2(acc[j][2], xx, w2);
                fma2(acc[j][3], xx, w3);
            }
        }
        if (c < 3) __syncthreads();
    }

    const unsigned long long* bp =
        reinterpret_cast<const unsigned long long*>(&sfb1[ht8]);
    float2 bb[4];
#pragma unroll
    for (int p = 0; p < 4; p++) bb[p] = unpack2(bp[p]);

    float* Hbase = g_H + ((size_t)(i * NB + b) * NVEC) * NHID;
#pragma unroll
    for (int j = 0; j < 4; j++) {
        float2 v0 = unpack2(acc[j][0]);
        float2 v1 = unpack2(acc[j][1]);
        float2 v2 = unpack2(acc[j][2]);
        float2 v3 = unpack2(acc[j][3]);
        float4 a = make_float4(gelu_exact(v0.x + bb[0].x), gelu_exact(v0.y + bb[0].y),
                               gelu_exact(v1.x + bb[1].x), gelu_exact(v1.y + bb[1].y));
        float4 cc = make_float4(gelu_exact(v2.x + bb[2].x), gelu_exact(v2.y + bb[2].y),
                                gelu_exact(v3.x + bb[3].x), gelu_exact(v3.y + bb[3].y));
        float* dst = Hbase + (size_t)(n0 + nb + j) * NHID + ht8;
        reinterpret_cast<float4*>(dst)[0] = a;
        reinterpret_cast<float4*>(dst)[1] = cc;
    }
}

// ---------------------------------------------------------------------------
// Kernel B: sparse W values. Block = (b, i), 1024 threads (t = n), 160 blocks.
// ---------------------------------------------------------------------------
#define FTS 36
#define W2_SMEM ((NVEC * FTS + NVEC) * 4)   // 151552 B

__global__ void __launch_bounds__(1024) w2_kernel(const float* __restrict__ fb2)
{
    extern __shared__ float sm[];
    float* sfT  = sm;              // [1024][36]
    float* sfb2 = sm + NVEC * FTS; // [1024]

    const int t = threadIdx.x;
    const int b = blockIdx.x;
    const int i = blockIdx.y;

    const float4* src4 =
        reinterpret_cast<const float4*>(g_fW2T + (size_t)i * NVEC * NHID);
#pragma unroll
    for (int q = 0; q < 8; q++) {
        int p = t + 1024 * q;
        float4 v = src4[p];
        int n = p >> 3, c = (p & 7) << 2;
        *reinterpret_cast<float4*>(&sfT[n * FTS + c]) = v;
    }
    sfb2[t] = __ldg(&fb2[i * NVEC + t]);

    float h[32];
    {
        const float4* hp = reinterpret_cast<const float4*>(
            g_H + ((size_t)(i * NB + b) * NVEC + t) * NHID);
#pragma unroll
        for (int q = 0; q < 8; q++) {
            float4 v = __ldg(hp + q);
            h[4 * q] = v.x; h[4 * q + 1] = v.y; h[4 * q + 2] = v.z; h[4 * q + 3] = v.w;
        }
    }
    __syncthreads();

    const int OFF[NOFF] = {0, 1, 2, 4, 8, 16, 32, 64, 128, 256, 512};
    float* out = g_w + (size_t)((i * NB + b) * NOFF) * NVEC + t;
#pragma unroll
    for (int o = 0; o < NOFF; o++) {
        int m = (t + OFF[o]) & (NVEC - 1);
        const float4* rp = reinterpret_cast<const float4*>(&sfT[m * FTS]);
        float s0 = 0.f, s1 = 0.f, s2 = 0.f, s3 = 0.f;
#pragma unroll
        for (int q = 0; q < 8; q++) {
            float4 w = rp[q];
            s0 = fmaf(h[4 * q],     w.x, s0);
            s1 = fmaf(h[4 * q + 1], w.y, s1);
            s2 = fmaf(h[4 * q + 2], w.z, s2);
            s3 = fmaf(h[4 * q + 3], w.w, s3);
        }
        out[(size_t)o * NVEC] = (s0 + s1) + (s2 + s3) + sfb2[m];
    }
}

// ---------------------------------------------------------------------------
// Kernel 2: 10-layer sparse recursion, VECTORIZED: block = (dg, b) owns 4 dims
// as float4 rows -> per offset ONE conflict-free LDS.128. 256 blocks,
// 2 CTAs/SM co-resident (33KB smem), 64 warps/SM for latency hiding.
// Fused output-GEMM epilogue + deterministic last-block reduction.
// ---------------------------------------------------------------------------
__global__ void __launch_bounds__(1024, 2) recurse_kernel(
    const float* __restrict__ data, const float* __restrict__ finb,
    float* __restrict__ out)
{
    __shared__ float4 Vs[2][NVEC];     // 32KB ping-pong
    __shared__ int isLast;
    const int t  = threadIdx.x;
    const int dg = blockIdx.x;         // 0..15 -> dims [4dg, 4dg+4)
    const int b  = blockIdx.y;

    float4 acc = __ldg(reinterpret_cast<const float4*>(
        data + ((size_t)(b * NVEC) + t) * NDIM + 4 * dg));
    Vs[0][t] = acc;

    const int OFF[NOFF] = {0, 1, 2, 4, 8, 16, 32, 64, 128, 256, 512};
    float wv[NOFF];
    {
        const float* w = g_w + (size_t)((9 * NB + b) * NOFF) * NVEC;
#pragma unroll
        for (int o = 0; o < NOFF; o++) wv[o] = __ldg(&w[o * NVEC + t]);
    }
    __syncthreads();

    int cur = 0;
#pragma unroll
    for (int i = NW - 1; i >= 0; i--) {
        float wn[NOFF];
        if (i > 0) {
            const float* w = g_w + (size_t)(((i - 1) * NB + b) * NOFF) * NVEC;
#pragma unroll
            for (int o = 0; o < NOFF; o++) wn[o] = __ldg(&w[o * NVEC + t]);
        }

        // residual + offset-0 from registers: na = acc + wv0*acc
        float4 na;
        na.x = fmaf(wv[0], acc.x, acc.x);
        na.y = fmaf(wv[0], acc.y, acc.y);
        na.z = fmaf(wv[0], acc.z, acc.z);
        na.w = fmaf(wv[0], acc.w, acc.w);
#pragma unroll
        for (int o = 1; o < NOFF; o++) {
            int m = (t + OFF[o]) & (NVEC - 1);
            float4 v = Vs[cur][m];                 // one LDS.128
            na.x = fmaf(wv[o], v.x, na.x);
            na.y = fmaf(wv[o], v.y, na.y);
            na.z = fmaf(wv[o], v.z, na.z);
            na.w = fmaf(wv[o], v.w, na.w);
        }
        Vs[cur ^ 1][t] = na;
        acc = na;
        __syncthreads();
        cur ^= 1;
#pragma unroll
        for (int o = 0; o < NOFF; o++) wv[o] = wn[o];
    }

    // ---- fused output GEMM epilogue: 4-dim dot vs g_fWT3[c][dg] ----
    const float4* W3 = reinterpret_cast<const float4*>(g_fWT3);
    float cs[10];
#pragma unroll
    for (int c = 0; c < 10; c++) {
        float4 w = __ldg(&W3[(c * 16 + dg) * 1024 + t]);
        cs[c] = acc.x * w.x + acc.y * w.y + acc.z * w.z + acc.w * w.w;
    }

#pragma unroll
    for (int c = 0; c < 10; c++) {
#pragma unroll
        for (int s = 16; s > 0; s >>= 1)
            cs[c] += __shfl_xor_sync(0xffffffffu, cs[c], s);
    }
    float* red = reinterpret_cast<float*>(&Vs[0][0]);
    int lane = t & 31, wp = t >> 5;
    if (lane == 0) {
#pragma unroll
        for (int c = 0; c < 10; c++) red[wp * 10 + c] = cs[c];
    }
    __syncthreads();
    if (t < 10) {
        float s = 0.f;
        for (int w_ = 0; w_ < 32; w_++) s += red[w_ * 10 + t];
        g_part[(b * 16 + dg) * 10 + t] = s;
    }
    __threadfence();
    if (t == 0) {
        int old = atomicAdd(&g_cnt, 1);
        isLast = (old == NB * 16 - 1);
    }
    __syncthreads();
    if (isLast) {
        __threadfence();
        if (t == 0) g_cnt = 0;
        if (t < NB * 10) {
            int bb = t / 10, c = t - bb * 10;
            float s = __ldg(&finb[c]);
#pragma unroll
            for (int cc = 0; cc < 16; cc++) s += g_part[(bb * 16 + cc) * 10 + c];
            out[t] = s;
        }
    }
}

// ---------------------------------------------------------------------------
extern "C" void kernel_launch(void* const* d_in, const int* in_sizes, int n_in,
                              void* d_out, int out_size)
{
    const float* data = (const float*)d_in[0];
    const float* fW1  = (const float*)d_in[1];
    const float* fb1  = (const float*)d_in[2];
    const float* fW2  = (const float*)d_in[3];
    const float* fb2  = (const float*)d_in[4];
    const float* finW = (const float*)d_in[5];
    const float* finb = (const float*)d_in[6];
    float* out = (float*)d_out;

    cudaFuncSetAttribute(h_kernel,
                         cudaFuncAttributeMaxDynamicSharedMemorySize, H_SMEM);
    cudaFuncSetAttribute(w2_kernel,
                         cudaFuncAttributeMaxDynamicSharedMemorySize, W2_SMEM);

    h_kernel<<<dim3(4, 16, 12), 256, H_SMEM>>>(data, fW1, fb1, fW2, finW);
    w2_kernel<<<dim3(16, 10), 1024, W2_SMEM>>>(fb2);
    recurse_kernel<<<dim3(16, 16), 1024>>>(data, finb, out);
}